// round 13
// baseline (speedup 1.0000x reference)
#include <cuda_runtime.h>
#include <cstdint>

// BoxFilter 9x9 zero-padded window sum. Fixed shape (8,3,1080,1920) fp32, r=4.
//
// v9 = v8 + single-wave geometry. v8's 900 blocks vs 888-slot capacity left a
// 12-block second wave (~10us at ~8% chip) that explains the 64% DRAM avg.
// Now: STRIP=120, NSTR=9 -> 810 blocks, all resident at t=0. DEPTH 6->8 for
// more outstanding bytes per warp (7 rows in flight).
//
// Pipeline: cp.async.cg streams each warp's 136-col input rows (center + both
// halos) into a DEPTH=8 smem stage ring; consume = 3 conflict-free LDS.128
// (p/v/n) + h-tree + vertical 9-row running sum (smem ring) + streaming STG.

#define RR 4
#define WD 1920
#define HD 1080
#define NIMG 24                  // B*C
#define TILE_W 128               // 32 lanes x float4
#define NTX 15                   // 1920/128
#define STRIP 120
#define NSTR 9                   // 1080/120
#define WPB 4
#define THREADS 128
#define NBLOCKS 810              // 24*15*9 warps / 4  (<= 888 = 148 SMs x 6)
#define RING 9
#define DEPTH 8                  // smem pipeline stages (input rows in flight)
#define CHUNKS 34                // 136 floats = 34 x 16B per stage row
#define NROWS (STRIP + 2 * RR)   // 128 input rows per strip

__device__ __forceinline__ float4 f4zero() { return make_float4(0.f, 0.f, 0.f, 0.f); }
__device__ __forceinline__ float4 add4(float4 a, float4 b) {
    return make_float4(a.x + b.x, a.y + b.y, a.z + b.z, a.w + b.w);
}
__device__ __forceinline__ float4 sub4(float4 a, float4 b) {
    return make_float4(a.x - b.x, a.y - b.y, a.z - b.z, a.w - b.w);
}

__global__ __launch_bounds__(THREADS, 6)
void boxfilter9x9_kernel(const float* __restrict__ x, float* __restrict__ out) {
    __shared__ float4 stage_sm[WPB][DEPTH][CHUNKS];   // 17,408 B
    __shared__ float4 ring_sm[WPB][RING][32];         // 18,432 B

    const int warp = threadIdx.x >> 5;
    const int lane = threadIdx.x & 31;
    const int gwarp = blockIdx.x * WPB + warp;

    const int strip = gwarp % NSTR;
    const int t     = gwarp / NSTR;
    const int tx    = t % NTX;
    const int img   = t / NTX;

    const float* __restrict__ base  = x   + (size_t)img * HD * WD;
    float* __restrict__       obase = out + (size_t)img * HD * WD;

    const int col0 = tx * TILE_W;
    const int row0 = strip * STRIP;

    // Zero all stages once: OOB halo chunks (left edge chunk0 / right edge
    // chunk33) are never refilled afterwards and must read as zero.
    for (int i = threadIdx.x; i < WPB * DEPTH * CHUNKS; i += THREADS)
        reinterpret_cast<float4*>(stage_sm)[i] = f4zero();
    __syncthreads();

    const bool skip_c0  = (tx == 0);        // chunk 0 would read cols -4..-1
    const bool skip_c33 = (tx == NTX - 1);  // chunk 33 would read cols 1920..1923

    float4 (* const mystage)[CHUNKS] = stage_sm[warp];
    float4* const myring = &ring_sm[warp][0][lane];   // slot stride = 32 float4

    // Stream input row ir into stage slot. Chunk c covers cols col0-4+4c.
    // Lane k -> chunk k; lanes 0,1 also chunks 32,33. Always commits a group
    // (empty groups complete immediately; keeps wait_group counts uniform).
    auto refill = [&](int ir, int slot) {
        if ((unsigned)ir < (unsigned)HD) {
            const float* rp = base + (size_t)ir * WD + (col0 - 4);  // 16B-aligned
            if (!(skip_c0 && lane == 0)) {
                unsigned d = (unsigned)__cvta_generic_to_shared(&mystage[slot][lane]);
                asm volatile("cp.async.cg.shared.global [%0], [%1], 16;"
                             :: "r"(d), "l"(rp + lane * 4));
            }
            if (lane < 2 && !(skip_c33 && lane == 1)) {
                unsigned d = (unsigned)__cvta_generic_to_shared(&mystage[slot][32 + lane]);
                asm volatile("cp.async.cg.shared.global [%0], [%1], 16;"
                             :: "r"(d), "l"(rp + (32 + lane) * 4));
            }
        } else {
            mystage[slot][lane] = f4zero();
            if (lane < 2) mystage[slot][32 + lane] = f4zero();
        }
        asm volatile("cp.async.commit_group;");
    };

    auto hsum = [&](float4 p, float4 v, float4 n) -> float4 {
        const float a0 = p.x, a1 = p.y, a2 = p.z, a3 = p.w;
        const float a4 = v.x, a5 = v.y, a6 = v.z, a7 = v.w;
        const float a8 = n.x, a9 = n.y, a10 = n.z, a11 = n.w;
        const float b0 = a0 + a1, b1 = a2 + a3, b2 = a4 + a5;
        const float b3 = a6 + a7, b4 = a8 + a9, b5 = a10 + a11;
        const float c0 = b0 + b1, c1 = b2 + b3, c2 = b4 + b5;
        float4 h;
        h.x = (c0 + c1) + a8;       // a0..a8
        h.w = (c1 + c2) + a3;       // a3..a11
        h.y = (h.x - a0) + a9;      // a1..a9
        h.z = (h.w - a11) + a2;     // a2..a10
        return h;
    };

    // ---- prologue A: fill pipeline with input rows 0..DEPTH-1 ----
#pragma unroll
    for (int k = 0; k < DEPTH; ++k) refill(row0 - RR + k, k);

    // ---- prologue B: consume input rows 0..7 -> ring[0..7] ----
    float4 vsum = f4zero();
    int ss = 0;                       // stage slot of next row to consume
#pragma unroll
    for (int k = 0; k < 2 * RR; ++k) {
        asm volatile("cp.async.wait_group %0;" :: "n"(DEPTH - 1));
        __syncwarp();
        float4 p = mystage[ss][lane];
        float4 v = mystage[ss][lane + 1];
        float4 n = mystage[ss][lane + 2];
        float4 h = hsum(p, v, n);
        myring[k * 32] = h;
        vsum = add4(vsum, h);
        refill(row0 - RR + k + DEPTH, ss);
        ss = (ss + 1 == DEPTH) ? 0 : ss + 1;
    }

    // ---- main loop: one output row per consumed input row ----
    int s_old = 0, s_new = 8;
    int i = row0;
#pragma unroll 2
    for (int k = 2 * RR; k < NROWS; ++k) {
        asm volatile("cp.async.wait_group %0;" :: "n"(DEPTH - 1));
        __syncwarp();
        float4 p = mystage[ss][lane];
        float4 v = mystage[ss][lane + 1];
        float4 n = mystage[ss][lane + 2];
        float4 h = hsum(p, v, n);          // h(i+4)

        float4 old = myring[s_old * 32];   // h(i-4)
        myring[s_new * 32] = h;

        vsum = add4(vsum, h);
        __stcs(reinterpret_cast<float4*>(obase + (size_t)i * WD + col0 + lane * 4), vsum);
        vsum = sub4(vsum, old);

        if (k + DEPTH < NROWS) refill(row0 - RR + k + DEPTH, ss);
        else asm volatile("cp.async.commit_group;");   // keep group count uniform

        ss = (ss + 1 == DEPTH) ? 0 : ss + 1;
        s_old = (s_old + 1 == RING) ? 0 : s_old + 1;
        s_new = (s_new + 1 == RING) ? 0 : s_new + 1;
        ++i;
    }
    asm volatile("cp.async.wait_group 0;");
}

extern "C" void kernel_launch(void* const* d_in, const int* in_sizes, int n_in,
                              void* d_out, int out_size) {
    const float* x = (const float*)d_in[0];
    // d_in[1] is r (int32, fixed at 4) — hardcoded.
    float* out = (float*)d_out;
    boxfilter9x9_kernel<<<NBLOCKS, THREADS>>>(x, out);
}

// round 14
// speedup vs baseline: 1.0527x; 1.0527x over previous
#include <cuda_runtime.h>
#include <cstdint>

// BoxFilter 9x9 zero-padded window sum. Fixed shape (8,3,1080,1920) fp32, r=4.
//
// v10: perfectly balanced persistent-style warps + register ring.
//  - Grid = 888 blocks (148 SMs x 6) x 128 thr = 3552 warps, all resident.
//  - Work = 360 column-strips x 1080 rows = 388800 row-units, split evenly:
//    warp w handles units [w*4050/37, (w+1)*4050/37)  (109-110 rows, <=2
//    segments when the range crosses a strip boundary). No wave tail, no
//    per-SM block-count imbalance (the v8/v9 limiter).
//  - cp.async.cg DEPTH=6 smem stage ring per warp (136-col rows: center+halos).
//  - Vertical 9-row running sum in REGISTERS (mod-9 unrolled slots) -> ring
//    smem traffic (1KB/row) removed from the L1tex crossbar budget.

#define RR 4
#define WD 1920
#define HD 1080
#define TILE_W 128               // 32 lanes x float4
#define NTX 15                   // 1920/128
#define WPB 4
#define THREADS 128
#define NBLOCKS 888              // 148 x 6
#define RING 9
#define DEPTH 6
#define CHUNKS 34                // 136 floats = 34 x 16B per stage row

__device__ __forceinline__ float4 f4zero() { return make_float4(0.f, 0.f, 0.f, 0.f); }
__device__ __forceinline__ float4 add4(float4 a, float4 b) {
    return make_float4(a.x + b.x, a.y + b.y, a.z + b.z, a.w + b.w);
}
__device__ __forceinline__ float4 sub4(float4 a, float4 b) {
    return make_float4(a.x - b.x, a.y - b.y, a.z - b.z, a.w - b.w);
}

__device__ __forceinline__ float4 hsum9(float4 p, float4 v, float4 n) {
    const float a0 = p.x, a1 = p.y, a2 = p.z, a3 = p.w;
    const float a4 = v.x, a5 = v.y, a6 = v.z, a7 = v.w;
    const float a8 = n.x, a9 = n.y, a10 = n.z, a11 = n.w;
    const float b0 = a0 + a1, b1 = a2 + a3, b2 = a4 + a5;
    const float b3 = a6 + a7, b4 = a8 + a9, b5 = a10 + a11;
    const float c0 = b0 + b1, c1 = b2 + b3, c2 = b4 + b5;
    float4 h;
    h.x = (c0 + c1) + a8;       // a0..a8
    h.w = (c1 + c2) + a3;       // a3..a11
    h.y = (h.x - a0) + a9;      // a1..a9
    h.z = (h.w - a11) + a2;     // a2..a10
    return h;
}

__global__ __launch_bounds__(THREADS, 6)
void boxfilter9x9_kernel(const float* __restrict__ x, float* __restrict__ out) {
    __shared__ float4 stage_sm[WPB][DEPTH][CHUNKS];   // 13,056 B / block

    const int warp = threadIdx.x >> 5;
    const int lane = threadIdx.x & 31;
    const int gwarp = blockIdx.x * WPB + warp;

    float4 (* const mystage)[CHUNKS] = stage_sm[warp];

    // Zero own stage once (covers OOB halo chunks for the first segment).
    for (int i2 = lane; i2 < DEPTH * CHUNKS; i2 += 32)
        (&mystage[0][0])[i2] = f4zero();
    __syncwarp();

    // Even split of 388800 row-units over 3552 warps (388800/3552 = 4050/37).
    uint64_t g  = (uint64_t)gwarp * 4050ull / 37ull;
    const uint64_t g1 = (uint64_t)(gwarp + 1) * 4050ull / 37ull;

    while (g < g1) {
        const uint32_t s     = (uint32_t)(g / 1080u);       // column-strip id
        const uint32_t r0    = (uint32_t)(g - (uint64_t)s * 1080u);
        const uint32_t avail = 1080u - r0;
        const uint32_t left  = (uint32_t)(g1 - g);
        const uint32_t nrows = (avail < left) ? avail : left;
        const uint32_t rend  = r0 + nrows;

        const uint32_t tx  = s % NTX;
        const uint32_t img = s / NTX;

        const float* __restrict__ base  = x   + (size_t)img * HD * WD;
        float* __restrict__       obase = out + (size_t)img * HD * WD;
        const int col0 = tx * TILE_W;
        const bool skip_c0  = (tx == 0);
        const bool skip_c33 = (tx == NTX - 1);

        // Halo chunks that refill will skip must be zero (may be stale from a
        // previous segment with a different tx).
        if (skip_c0  && lane < DEPTH) mystage[lane][0]  = f4zero();
        if (skip_c33 && lane < DEPTH) mystage[lane][33] = f4zero();
        __syncwarp();

        // Stream input row ir into stage slot; always commits a group.
        auto refill = [&](int ir, int slot) {
            if ((unsigned)ir < (unsigned)HD) {
                const float* rp = base + (size_t)ir * WD + (col0 - 4);  // 16B-aligned
                if (!(skip_c0 && lane == 0)) {
                    unsigned d = (unsigned)__cvta_generic_to_shared(&mystage[slot][lane]);
                    asm volatile("cp.async.cg.shared.global [%0], [%1], 16;"
                                 :: "r"(d), "l"(rp + lane * 4));
                }
                if (lane < 2 && !(skip_c33 && lane == 1)) {
                    unsigned d = (unsigned)__cvta_generic_to_shared(&mystage[slot][32 + lane]);
                    asm volatile("cp.async.cg.shared.global [%0], [%1], 16;"
                                 :: "r"(d), "l"(rp + (32 + lane) * 4));
                }
            } else {
                mystage[slot][lane] = f4zero();
                if (lane < 2) mystage[slot][32 + lane] = f4zero();
            }
            asm volatile("cp.async.commit_group;");
        };

        // ---- prologue A: fill pipeline with first DEPTH input rows ----
#pragma unroll
        for (int k = 0; k < DEPTH; ++k) refill((int)r0 - RR + k, k);

        // ---- prologue B: consume 8 input rows -> register ring[0..7] ----
        float4 ring[RING];
        float4 vsum = f4zero();
        int ss = 0;
#pragma unroll
        for (int k = 0; k < 2 * RR; ++k) {
            asm volatile("cp.async.wait_group %0;" :: "n"(DEPTH - 1));
            __syncwarp();
            float4 p = mystage[ss][lane];
            float4 v = mystage[ss][lane + 1];
            float4 n = mystage[ss][lane + 2];
            float4 h = hsum9(p, v, n);
            ring[k] = h;
            vsum = add4(vsum, h);
            refill((int)r0 - RR + k + DEPTH, ss);
            ss = (ss + 1 == DEPTH) ? 0 : ss + 1;
        }
        ring[8] = f4zero();   // defined value; overwritten before first use

        // ---- main: one output row per consumed input row ----
        int irow = (int)r0;
        const int end = (int)rend;
        while (irow < end) {
#pragma unroll
            for (int u = 0; u < RING; ++u) {
                if (irow < end) {
                    asm volatile("cp.async.wait_group %0;" :: "n"(DEPTH - 1));
                    __syncwarp();
                    float4 p = mystage[ss][lane];
                    float4 v = mystage[ss][lane + 1];
                    float4 n = mystage[ss][lane + 2];
                    float4 h = hsum9(p, v, n);       // h(irow+4)

                    float4 old = ring[u];            // h(irow-4): j == u (mod 9)
                    ring[(u + 2 * RR) % RING] = h;   // compile-time slot

                    vsum = add4(vsum, h);
                    __stcs(reinterpret_cast<float4*>(
                               obase + (size_t)irow * WD + col0 + lane * 4), vsum);
                    vsum = sub4(vsum, old);

                    if (irow + DEPTH < end) refill(irow + RR + DEPTH, ss);
                    else asm volatile("cp.async.commit_group;");  // uniform count

                    ss = (ss + 1 == DEPTH) ? 0 : ss + 1;
                    ++irow;
                }
            }
        }

        // Drain before slots are reused by the next segment.
        asm volatile("cp.async.wait_group 0;");
        __syncwarp();

        g += nrows;
    }
}

extern "C" void kernel_launch(void* const* d_in, const int* in_sizes, int n_in,
                              void* d_out, int out_size) {
    const float* x = (const float*)d_in[0];
    // d_in[1] is r (int32, fixed at 4) — hardcoded.
    float* out = (float*)d_out;
    boxfilter9x9_kernel<<<NBLOCKS, THREADS>>>(x, out);
}